// round 14
// baseline (speedup 1.0000x reference)
#include <cuda_runtime.h>
#include <cuda_bf16.h>
#include <math.h>
#include <stdint.h>

// ---------------- problem constants ----------------
#define BB      8
#define NTOK    1568
#define CC      256
#define HID     1024
#define HH      56
#define HWSZ    (HH*HH)        // 3136
#define MKV     784            // 28*28
#define HEADS   8
#define DH      32
#define HINIT   112
#define BN      (BB*NTOK)      // 12544
#define BHW     (BB*HWSZ)      // 25088
#define BM      (BB*MKV)       // 6272
#define W4      (1.0f/(4.0f+1e-6f))
#define LN_EPS  1e-5f
#define EPS_C   1e-6f
#define CAP     64

// weight split buffer offsets (elements)
#define OFF_Q   0
#define OFF_SR  65536
#define OFF_KV  327680
#define OFF_PJ  458752
#define OFF_F1  524288
#define OFF_F2  786432
#define WTOT    1048576

typedef unsigned long long u64;

// ---------------- scratch (device globals) ----------------
__device__ float g_xn   [BN*CC];
__device__ float g_q    [BN*CC];
__device__ float g_kvmap[BHW*CC];
__device__ float g_conf [BM];
__device__ float g_kvcv [BM*CC];
__device__ float g_kv2  [BM*2*CC];
__device__ float g_x2   [BN*CC];
__device__ float g_h    [BN*HID];
__device__ float g_hmap [BHW*HID];
__device__ float g_dw   [BHW*HID];
__device__ int   g_tcnt [BN];
__device__ int   g_tsrc [BN*CAP];
__device__ __nv_bfloat16 g_ah [BN*HID];
__device__ __nv_bfloat16 g_al [BN*HID];
__device__ __nv_bfloat16 g_wh [WTOT];
__device__ __nv_bfloat16 g_wl [WTOT];

// ---------------- f32x2 packed-math helpers ----------------
__device__ __forceinline__ u64 pack2(float lo, float hi) {
    u64 r; asm("mov.b64 %0, {%1, %2};" : "=l"(r) : "f"(lo), "f"(hi)); return r;
}
__device__ __forceinline__ u64 pack2s(float v) { return pack2(v, v); }
__device__ __forceinline__ void unpack2(u64 p, float& lo, float& hi) {
    asm("mov.b64 {%0, %1}, %2;" : "=f"(lo), "=f"(hi) : "l"(p));
}
__device__ __forceinline__ u64 fma2(u64 a, u64 b, u64 c) {
    u64 d; asm("fma.rn.f32x2 %0, %1, %2, %3;" : "=l"(d) : "l"(a), "l"(b), "l"(c)); return d;
}

__device__ __forceinline__ float warp_sum(float v) {
#pragma unroll
    for (int o = 16; o > 0; o >>= 1) v += __shfl_down_sync(0xffffffffu, v, o);
    return v;
}

__device__ __forceinline__ void split_bf(float v, __nv_bfloat16& hi, __nv_bfloat16& lo) {
    hi = __float2bfloat16(v);
    lo = __float2bfloat16(v - __bfloat162float(hi));
}

// ---------------- mma.sync / cp.async helpers ----------------
__device__ __forceinline__ uint32_t s2u(const void* p) {
    uint32_t a;
    asm("{ .reg .u64 t; cvta.to.shared.u64 t, %1; cvt.u32.u64 %0, t; }" : "=r"(a) : "l"(p));
    return a;
}
__device__ __forceinline__ void ldsm4(uint32_t* r, uint32_t addr) {
    asm volatile("ldmatrix.sync.aligned.m8n8.x4.shared.b16 {%0,%1,%2,%3}, [%4];"
                 : "=r"(r[0]), "=r"(r[1]), "=r"(r[2]), "=r"(r[3]) : "r"(addr));
}
__device__ __forceinline__ void mma_bf16(float* d, const uint32_t* a, const uint32_t* b) {
    asm volatile("mma.sync.aligned.m16n8k16.row.col.f32.bf16.bf16.f32 "
                 "{%0,%1,%2,%3}, {%4,%5,%6,%7}, {%8,%9}, {%0,%1,%2,%3};"
                 : "+f"(d[0]), "+f"(d[1]), "+f"(d[2]), "+f"(d[3])
                 : "r"(a[0]), "r"(a[1]), "r"(a[2]), "r"(a[3]), "r"(b[0]), "r"(b[1]));
}
__device__ __forceinline__ void cp16(uint32_t dst, const void* src) {
    asm volatile("cp.async.cg.shared.global [%0], [%1], 16;" :: "r"(dst), "l"(src));
}
__device__ __forceinline__ void cp_commit() { asm volatile("cp.async.commit_group;" ::: "memory"); }
__device__ __forceinline__ void cp_wait1()  { asm volatile("cp.async.wait_group 1;"  ::: "memory"); }
__device__ __forceinline__ void cp_wait0()  { asm volatile("cp.async.wait_group 0;"  ::: "memory"); }

// ---------------- tensor-core split-bf16 GEMM (double-buffered cp.async) ----------
#define RS  80
#define STG (4*128*RS)
template<int EPI, int GATHER>
__global__ void __launch_bounds__(256, 2)
tc_gemm(const __nv_bfloat16* __restrict__ Ah, const __nv_bfloat16* __restrict__ Al,
        const __nv_bfloat16* __restrict__ Wh, const __nv_bfloat16* __restrict__ Wl,
        const float* __restrict__ bias, const float* __restrict__ res,
        float* __restrict__ out, int M, int K, int Nc, const float* __restrict__ gsrc) {
    extern __shared__ __align__(16) char sm[];
    const int O_AL = 128 * RS, O_BH = 2 * 128 * RS, O_BL = 3 * 128 * RS;

    int tid = threadIdx.x, wid = tid >> 5, lane = tid & 31;
    int mw = wid >> 1, wc = wid & 1;
    long row0 = (long)blockIdx.y * 128, col0 = (long)blockIdx.x * 128;

    uint32_t sb = s2u(sm);
    int q = lane >> 3, l7 = lane & 7;
    int a_row = mw * 32 + ((q & 1) << 3) + l7;
    int a_kb  = (q >> 1) << 3;
    int b_row = wc * 64 + ((q >> 1) << 3) + l7;
    int b_kb  = (q & 1) << 3;

    float4 pref[2][2];

    auto issueB = [&](int ch, int st) {
        char* base = sm + st * STG;
        long k0 = (long)ch << 5;
#pragma unroll
        for (int it = 0; it < 2; it++) {
            int slot = tid + it * 256, r = slot >> 2, u = slot & 3;
            int so = r * RS + u * 16;
            long gb = (col0 + r) * K + k0 + u * 8;
            cp16(s2u(base + O_BH + so), Wh + gb);
            cp16(s2u(base + O_BL + so), Wl + gb);
        }
    };
    auto issueA = [&](int ch, int st) {
        char* base = sm + st * STG;
        long k0 = (long)ch << 5;
#pragma unroll
        for (int it = 0; it < 2; it++) {
            int slot = tid + it * 256, r = slot >> 2, u = slot & 3;
            int so = r * RS + u * 16;
            long ga = (row0 + r) * K + k0 + u * 8;
            cp16(s2u(base + so), Ah + ga);
            cp16(s2u(base + O_AL + so), Al + ga);
        }
    };
    auto prefA = [&](int ch) {
        long k0 = (long)ch << 5;
#pragma unroll
        for (int it = 0; it < 2; it++) {
            int slot = tid + it * 256, r = slot >> 2, u = slot & 3;
            long row = row0 + r;
            int kg = (int)k0 + u * 8;
            int b = (int)(row / MKV), m = (int)(row - (long)b * MKV);
            int r2 = m / 28, c2 = m - r2 * 28;
            int di = kg >> 9, dj = (kg >> 8) & 1, ci = kg & 255;
            const float* src = gsrc + (((size_t)b * HWSZ) + (2 * r2 + di) * HH + (2 * c2 + dj)) * CC + ci;
            pref[it][0] = *(const float4*)src;
            pref[it][1] = *(const float4*)(src + 4);
        }
    };
    auto storeA = [&](int st) {
        char* base = sm + st * STG;
#pragma unroll
        for (int it = 0; it < 2; it++) {
            int slot = tid + it * 256, r = slot >> 2, u = slot & 3;
            int so = r * RS + u * 16;
            float f[8] = {pref[it][0].x, pref[it][0].y, pref[it][0].z, pref[it][0].w,
                          pref[it][1].x, pref[it][1].y, pref[it][1].z, pref[it][1].w};
            __align__(16) __nv_bfloat16 hb[8], lb[8];
#pragma unroll
            for (int e = 0; e < 8; e++) split_bf(f[e], hb[e], lb[e]);
            *(uint4*)(base + so)        = *(uint4*)hb;
            *(uint4*)(base + O_AL + so) = *(uint4*)lb;
        }
    };

    float acc[2][8][4];
#pragma unroll
    for (int i = 0; i < 2; i++)
#pragma unroll
        for (int j = 0; j < 8; j++)
#pragma unroll
            for (int k = 0; k < 4; k++) acc[i][j][k] = 0.f;

    int nch = K >> 5;
    if (GATHER) prefA(0); else issueA(0, 0);
    issueB(0, 0);
    cp_commit();

    for (int ch = 0; ch < nch; ch++) {
        int s = ch & 1;
        if (GATHER) storeA(s);
        if (ch + 1 < nch) {
            if (!GATHER) issueA(ch + 1, s ^ 1);
            issueB(ch + 1, s ^ 1);
            cp_commit();
            if (GATHER) prefA(ch + 1);
            cp_wait1();
        } else {
            cp_wait0();
        }
        __syncthreads();

        uint32_t sbase = sb + s * STG;
#pragma unroll
        for (int ks = 0; ks < 2; ks++) {
            uint32_t ahf[2][4], alf[2][4];
#pragma unroll
            for (int mi = 0; mi < 2; mi++) {
                uint32_t ao = (uint32_t)((a_row + mi * 16) * RS + (ks * 16 + a_kb) * 2);
                ldsm4(ahf[mi], sbase + ao);
                ldsm4(alf[mi], sbase + O_AL + ao);
            }
#pragma unroll
            for (int ng = 0; ng < 4; ng++) {
                uint32_t bh[4], bl[4];
                uint32_t bo = (uint32_t)((b_row + ng * 16) * RS + (ks * 16 + b_kb) * 2);
                ldsm4(bh, sbase + O_BH + bo);
                ldsm4(bl, sbase + O_BL + bo);
#pragma unroll
                for (int mi = 0; mi < 2; mi++) {
                    mma_bf16(acc[mi][ng * 2],     ahf[mi], bh);
                    mma_bf16(acc[mi][ng * 2 + 1], ahf[mi], bh + 2);
                    mma_bf16(acc[mi][ng * 2],     ahf[mi], bl);
                    mma_bf16(acc[mi][ng * 2 + 1], ahf[mi], bl + 2);
                    mma_bf16(acc[mi][ng * 2],     alf[mi], bh);
                    mma_bf16(acc[mi][ng * 2 + 1], alf[mi], bh + 2);
                }
            }
        }
        __syncthreads();
    }

    int r_lane = lane >> 2, c_lane = (lane & 3) << 1;
#pragma unroll
    for (int mi = 0; mi < 2; mi++) {
#pragma unroll
        for (int ni = 0; ni < 8; ni++) {
            long r = row0 + mw * 32 + mi * 16 + r_lane;
            long c = col0 + wc * 64 + ni * 8 + c_lane;
            float b0 = bias[c], b1 = bias[c + 1];
            float2 v0 = {acc[mi][ni][0] + b0, acc[mi][ni][1] + b1};
            float2 v1 = {acc[mi][ni][2] + b0, acc[mi][ni][3] + b1};
            if (EPI == 1) {
                float2 r0 = *(const float2*)(res + r * Nc + c);
                float2 r1 = *(const float2*)(res + (r + 8) * Nc + c);
                v0.x += r0.x; v0.y += r0.y;
                v1.x += r1.x; v1.y += r1.y;
            }
            *(float2*)(out + r * Nc + c) = v0;
            *(float2*)(out + (r + 8) * Nc + c) = v1;
        }
    }
}

// ---------------- batched weight transpose+split: all 6 weights, one launch ----------
__global__ void wsplit_all(const float* __restrict__ q_w,  const float* __restrict__ sr_w,
                           const float* __restrict__ kv_w, const float* __restrict__ proj_w,
                           const float* __restrict__ fc1_w,const float* __restrict__ fc2_w) {
    const float* W; int K, N; size_t off;
    switch (blockIdx.z) {
        case 0:  W = q_w;    K = 256;  N = 256;  off = OFF_Q;  break;
        case 1:  W = sr_w;   K = 1024; N = 256;  off = OFF_SR; break;
        case 2:  W = kv_w;   K = 256;  N = 512;  off = OFF_KV; break;
        case 3:  W = proj_w; K = 256;  N = 256;  off = OFF_PJ; break;
        case 4:  W = fc1_w;  K = 256;  N = 1024; off = OFF_F1; break;
        default: W = fc2_w;  K = 1024; N = 256;  off = OFF_F2; break;
    }
    int nb = blockIdx.x * 32, kb = blockIdx.y * 32;
    if (nb >= N || kb >= K) return;
    __shared__ float t[32][33];
    int tx = threadIdx.x, ty = threadIdx.y;
    t[ty][tx] = W[(size_t)(kb + ty) * N + nb + tx];
    __syncthreads();
    float v = t[tx][ty];
    __nv_bfloat16 hi, lo;
    split_bf(v, hi, lo);
    size_t o = off + (size_t)(nb + ty) * K + kb + tx;
    g_wh[o] = hi;
    g_wl[o] = lo;
}

// ---------------- LayerNorm over 256 cols ----------------
template<int WF32, int WSPL>
__global__ void ln256_kernel(const float* __restrict__ in, float* __restrict__ out,
                             const float* __restrict__ w, const float* __restrict__ b) {
    int row = blockIdx.x;
    int tid = threadIdx.x;
    float v = in[(size_t)row * CC + tid];
    __shared__ float red[8];
    __shared__ float s_mean, s_rstd;
    float s = warp_sum(v);
    int lane = tid & 31, wid = tid >> 5;
    if (lane == 0) red[wid] = s;
    __syncthreads();
    if (tid == 0) {
        float t = 0.f;
#pragma unroll
        for (int i = 0; i < 8; i++) t += red[i];
        s_mean = t * (1.0f / CC);
    }
    __syncthreads();
    float xc = v - s_mean;
    float s2 = warp_sum(xc * xc);
    if (lane == 0) red[wid] = s2;
    __syncthreads();
    if (tid == 0) {
        float t = 0.f;
#pragma unroll
        for (int i = 0; i < 8; i++) t += red[i];
        s_rstd = rsqrtf(t * (1.0f / CC) + LN_EPS);
    }
    __syncthreads();
    float o = xc * s_rstd * w[tid] + b[tid];
    size_t g = (size_t)row * CC + tid;
    if (WF32) out[g] = o;
    if (WSPL) {
        __nv_bfloat16 hi, lo;
        split_bf(o, hi, lo);
        g_ah[g] = hi;
        g_al[g] = lo;
    }
}

// ---------------- token2map tmp + fused conf: one 2x2 pixel block per CTA ----------
__global__ void t2m_tmp_kernel(const float* __restrict__ xn, const float* __restrict__ tscore,
                               const int* __restrict__ idx) {
    int g = blockIdx.x;                   // b*MKV + m  (2x2 block id)
    int b = g / MKV, m = g - b * MKV;
    int r2 = m / 28, c2 = m - r2 * 28;
    int p = threadIdx.x >> 6;             // 0..3 : (dy,dx)
    int dy = p >> 1, dx = p & 1;
    int t = threadIdx.x & 63;
    int hw = (2 * r2 + dy) * HH + 2 * c2 + dx;
    int gi = (2 * (2 * r2 + dy)) * HINIT + 2 * (2 * c2 + dx);
    const int* ib = idx + (size_t)b * (HINIT * HINIT);
    int t0 = ib[gi], t1 = ib[gi + 1], t2 = ib[gi + HINIT], t3 = ib[gi + HINIT + 1];
    const float4* x0 = (const float4*)(xn + ((size_t)b * NTOK + t0) * CC);
    const float4* x1 = (const float4*)(xn + ((size_t)b * NTOK + t1) * CC);
    const float4* x2 = (const float4*)(xn + ((size_t)b * NTOK + t2) * CC);
    const float4* x3 = (const float4*)(xn + ((size_t)b * NTOK + t3) * CC);
    float4 a = x0[t], b4 = x1[t], c4 = x2[t], d4 = x3[t];
    float4 o;
    o.x = W4 * (a.x + b4.x + c4.x + d4.x);
    o.y = W4 * (a.y + b4.y + c4.y + d4.y);
    o.z = W4 * (a.z + b4.z + c4.z + d4.z);
    o.w = W4 * (a.w + b4.w + c4.w + d4.w);
    ((float4*)(g_kvmap + ((size_t)b * HWSZ + hw) * CC))[t] = o;
    __shared__ float cf[4];
    if (t == 0) {
        const float* ts = tscore + (size_t)b * NTOK;
        cf[p] = W4 * (ts[t0] + ts[t1] + ts[t2] + ts[t3]);
    }
    __syncthreads();
    if (threadIdx.x == 0)
        g_conf[g] = 0.25f * (cf[0] + cf[1] + cf[2] + cf[3]);
}

// ---------------- fused attention: branchy online softmax, f32x2 ----------------
__global__ void attn_kernel(const float* __restrict__ q, const float* __restrict__ kv2,
                            const float* __restrict__ conf) {
    const int KT = 112;
    const int DP = DH / 2;
    int bh = blockIdx.x;
    int b = bh / HEADS, h = bh - b * HEADS;
    int n = blockIdx.y * 128 + threadIdx.x;
    bool valid = n < NTOK;
    __shared__ float ksh[KT][DH];
    __shared__ float vsh[KT][DH];
    __shared__ float csh[KT];
    const float scale = 0.17677669529663687f;
    u64 q2[DP], oa2[DP];
#pragma unroll
    for (int k = 0; k < DP; k++) { q2[k] = 0ull; oa2[k] = 0ull; }
    if (valid) {
        const float* qp = q + ((size_t)b * NTOK + n) * CC + h * DH;
#pragma unroll
        for (int k = 0; k < DP; k++) q2[k] = pack2(qp[2 * k] * scale, qp[2 * k + 1] * scale);
    }
    float mrun = -1e30f, lrun = 0.f;
    for (int t = 0; t < 7; t++) {
        int m0 = t * KT;
        __syncthreads();
        for (int i = threadIdx.x; i < KT * DH; i += 128) {
            int mm = i / DH, dd = i - mm * DH;
            size_t base = ((size_t)b * MKV + m0 + mm) * (2 * CC) + h * DH + dd;
            ksh[mm][dd] = kv2[base];
            vsh[mm][dd] = kv2[base + CC];
        }
        if (threadIdx.x < KT) csh[threadIdx.x] = conf[(size_t)b * MKV + m0 + threadIdx.x];
        __syncthreads();
        for (int j = 0; j < KT; j++) {
            const u64* kp = (const u64*)&ksh[j][0];
            u64 s2 = 0ull;
#pragma unroll
            for (int k = 0; k < DP; k++) s2 = fma2(q2[k], kp[k], s2);
            float slo, shi;
            unpack2(s2, slo, shi);
            float s = slo + shi + csh[j];
            const u64* vp = (const u64*)&vsh[j][0];
            if (s <= mrun) {
                float p = __expf(s - mrun);
                lrun += p;
                u64 p2 = pack2s(p);
#pragma unroll
                for (int k = 0; k < DP; k++) oa2[k] = fma2(p2, vp[k], oa2[k]);
            } else {
                float corr = __expf(mrun - s);
                lrun = lrun * corr + 1.0f;
                u64 corr2 = pack2s(corr);
#pragma unroll
                for (int k = 0; k < DP; k++) oa2[k] = fma2(oa2[k], corr2, vp[k]);
                mrun = s;
            }
        }
    }
    if (valid) {
        float inv = 1.0f / lrun;
        size_t op = ((size_t)b * NTOK + n) * CC + h * DH;
#pragma unroll
        for (int k = 0; k < DP; k++) {
            float lo, hi;
            unpack2(oa2[k], lo, hi);
            __nv_bfloat16 h0, l0, h1, l1;
            split_bf(lo * inv, h0, l0);
            split_bf(hi * inv, h1, l1);
            g_ah[op + 2 * k] = h0;  g_al[op + 2 * k] = l0;
            g_ah[op + 2 * k + 1] = h1;  g_al[op + 2 * k + 1] = l1;
        }
    }
}

// ---------------- token2map for h (1024 ch), float4 ----------------
__global__ void t2m_h_kernel(const float* __restrict__ hin, const int* __restrict__ idx) {
    int blk = blockIdx.x;
    int b = blk / HWSZ, hw = blk - b * HWSZ;
    int r = hw / HH, c = hw - r * HH;
    int gi = (2 * r) * HINIT + 2 * c;
    const int* ib = idx + (size_t)b * (HINIT * HINIT);
    int t0 = ib[gi], t1 = ib[gi + 1], t2 = ib[gi + HINIT], t3 = ib[gi + HINIT + 1];
    const float4* x0 = (const float4*)(hin + ((size_t)b * NTOK + t0) * HID);
    const float4* x1 = (const float4*)(hin + ((size_t)b * NTOK + t1) * HID);
    const float4* x2 = (const float4*)(hin + ((size_t)b * NTOK + t2) * HID);
    const float4* x3 = (const float4*)(hin + ((size_t)b * NTOK + t3) * HID);
    float4* o = (float4*)(g_hmap + (size_t)blk * HID);
    int t = threadIdx.x;
    float4 a = x0[t], b4 = x1[t], c4 = x2[t], d4 = x3[t];
    float4 v;
    v.x = W4 * (a.x + b4.x + c4.x + d4.x);
    v.y = W4 * (a.y + b4.y + c4.y + d4.y);
    v.z = W4 * (a.z + b4.z + c4.z + d4.z);
    v.w = W4 * (a.w + b4.w + c4.w + d4.w);
    o[t] = v;
}

// ---------------- tiled depthwise 3x3: 8x8 spatial x 128ch, smem halo reuse -------
// grid (49, 8, 8) = (tile, ch-slice, batch), block 256, dyn smem 100*32*16 = 51200 B
__global__ void dwconv_tiled(const float* __restrict__ dww, const float* __restrict__ dwb) {
    extern __shared__ float4 sh[];   // [100][32]
    int tile = blockIdx.x, slice = blockIdx.y, b = blockIdx.z;
    int ty0 = (tile / 7) * 8, tx0 = (tile % 7) * 8;
    const float4* hb = (const float4*)(g_hmap + (size_t)b * HWSZ * HID);
    // load 10x10 halo (128 ch = 32 float4)
    for (int i = threadIdx.x; i < 3200; i += 256) {
        int px = i >> 5, cl = i & 31;
        int hy = ty0 + (px / 10) - 1, hx = tx0 + (px % 10) - 1;
        float4 v = {0.f, 0.f, 0.f, 0.f};
        if (hy >= 0 && hy < HH && hx >= 0 && hx < HH)
            v = hb[(size_t)(hy * HH + hx) * 256 + slice * 32 + cl];
        sh[px * 32 + cl] = v;
    }
    __syncthreads();
    int cl = threadIdx.x & 31;
    int pr = threadIdx.x >> 5;     // row 0..7 within tile
    int cg = slice * 32 + cl;      // global float4 channel index
    float4 wreg[9];
#pragma unroll
    for (int j = 0; j < 9; j++) wreg[j] = ((const float4*)dww)[j * 256 + cg];
    float4 bias = ((const float4*)dwb)[cg];
    float4* ob = (float4*)(g_dw + (size_t)b * HWSZ * HID);
#pragma unroll
    for (int pc = 0; pc < 8; pc++) {
        float4 acc = bias;
#pragma unroll
        for (int ky = 0; ky < 3; ky++)
#pragma unroll
            for (int kx = 0; kx < 3; kx++) {
                float4 in = sh[((pr + ky) * 10 + pc + kx) * 32 + cl];
                float4 w = wreg[ky * 3 + kx];
                acc.x = fmaf(in.x, w.x, acc.x);
                acc.y = fmaf(in.y, w.y, acc.y);
                acc.z = fmaf(in.z, w.z, acc.z);
                acc.w = fmaf(in.w, w.w, acc.w);
            }
        ob[(size_t)((ty0 + pr) * HH + tx0 + pc) * 256 + cg] = acc;
    }
}

// ---------------- map2token: token source lists ----------------
__global__ void fillint0_kernel(int* p, int n) {
    int g = blockIdx.x * blockDim.x + threadIdx.x;
    if (g < n) p[g] = 0;
}

__global__ void build_src_kernel(const int* __restrict__ idx) {
    int g = blockIdx.x * blockDim.x + threadIdx.x;
    if (g >= BB * HINIT * HINIT) return;
    int b = g / (HINIT * HINIT), i = g - b * (HINIT * HINIT);
    int tok = idx[(size_t)b * HINIT * HINIT + i];
    int ir = i / HINIT, ic = i - ir * HINIT;
    int hw = (ir >> 1) * HH + (ic >> 1);
    int row = b * NTOK + tok;
    int slot = atomicAdd(&g_tcnt[row], 1);
    if (slot < CAP) g_tsrc[row * CAP + slot] = hw;
}

__global__ void hc_gather_kernel(const float* __restrict__ skipw) {
    int row = blockIdx.x;
    int b = row / NTOK;
    int c4 = threadIdx.x;
    int cnt = g_tcnt[row];
    const float4* dwb = (const float4*)(g_dw + (size_t)b * HWSZ * HID);
    float4 acc = {0.f, 0.f, 0.f, 0.f};
    for (int s = 0; s < cnt; s++) {
        int hw = g_tsrc[row * CAP + s];
        float4 v = dwb[(size_t)hw * 256 + c4];
        acc.x += v.x; acc.y += v.y; acc.z += v.z; acc.w += v.w;
    }
    float inv = 1.0f / ((float)cnt + EPS_C);
    float4 hv = ((const float4*)g_h)[(size_t)row * 256 + c4];
    float4 sw = ((const float4*)skipw)[c4];
    float v[4];
    v[0] = hv.x * sw.x + acc.x * inv;
    v[1] = hv.y * sw.y + acc.y * inv;
    v[2] = hv.z * sw.z + acc.z * inv;
    v[3] = hv.w * sw.w + acc.w * inv;
    __align__(8) __nv_bfloat16 hb[4], lb[4];
#pragma unroll
    for (int e = 0; e < 4; e++) {
        float gv = 0.5f * v[e] * (1.0f + erff(v[e] * 0.70710678118654752f));
        split_bf(gv, hb[e], lb[e]);
    }
    size_t o = (size_t)row * HID + c4 * 4;
    *(uint2*)(g_ah + o) = *(uint2*)hb;
    *(uint2*)(g_al + o) = *(uint2*)lb;
}

// ---------------- launch ----------------
extern "C" void kernel_launch(void* const* d_in, const int* in_sizes, int n_in,
                              void* d_out, int out_size) {
    const float* x       = (const float*)d_in[0];
    const float* tscore  = (const float*)d_in[1];
    const int*   idx     = (const int*)  d_in[2];
    const float* n1w     = (const float*)d_in[3];
    const float* n1b     = (const float*)d_in[4];
    const float* q_w     = (const float*)d_in[5];
    const float* q_b     = (const float*)d_in[6];
    const float* kv_w    = (const float*)d_in[7];
    const float* kv_b    = (const float*)d_in[8];
    const float* sr_w    = (const float*)d_in[9];
    const float* sr_b    = (const float*)d_in[10];
    const float* srn_w   = (const float*)d_in[11];
    const float* srn_b   = (const float*)d_in[12];
    const float* proj_w  = (const float*)d_in[13];
    const float* proj_b  = (const float*)d_in[14];
    const float* n2w     = (const float*)d_in[15];
    const float* n2b     = (const float*)d_in[16];
    const float* fc1_w   = (const float*)d_in[17];
    const float* fc1_b   = (const float*)d_in[18];
    const float* skip_w  = (const float*)d_in[19];
    const float* dw_w    = (const float*)d_in[20];
    const float* dw_b    = (const float*)d_in[21];
    const float* fc2_w   = (const float*)d_in[22];
    const float* fc2_b   = (const float*)d_in[23];
    float* out = (float*)d_out;

    float *xn, *q, *kvcv, *kv2, *x2, *h, *conf, *kvmap;
    int *tcnt;
    __nv_bfloat16 *ah, *al, *wh, *wl;
    cudaGetSymbolAddress((void**)&xn,    g_xn);
    cudaGetSymbolAddress((void**)&q,     g_q);
    cudaGetSymbolAddress((void**)&kvcv,  g_kvcv);
    cudaGetSymbolAddress((void**)&kv2,   g_kv2);
    cudaGetSymbolAddress((void**)&x2,    g_x2);
    cudaGetSymbolAddress((void**)&h,     g_h);
    cudaGetSymbolAddress((void**)&conf,  g_conf);
    cudaGetSymbolAddress((void**)&kvmap, g_kvmap);
    cudaGetSymbolAddress((void**)&tcnt,  g_tcnt);
    cudaGetSymbolAddress((void**)&ah,    g_ah);
    cudaGetSymbolAddress((void**)&al,    g_al);
    cudaGetSymbolAddress((void**)&wh,    g_wh);
    cudaGetSymbolAddress((void**)&wl,    g_wl);

    const int DSM = 2 * STG;   // 81920 B
    cudaFuncSetAttribute(tc_gemm<0, 0>, cudaFuncAttributeMaxDynamicSharedMemorySize, DSM);
    cudaFuncSetAttribute(tc_gemm<1, 0>, cudaFuncAttributeMaxDynamicSharedMemorySize, DSM);
    cudaFuncSetAttribute(tc_gemm<0, 1>, cudaFuncAttributeMaxDynamicSharedMemorySize, DSM);
    cudaFuncSetAttribute(dwconv_tiled, cudaFuncAttributeMaxDynamicSharedMemorySize, 51200);

    // independent prep: token source lists + all weight splits
    fillint0_kernel<<<(BN + 255) / 256, 256>>>(tcnt, BN);
    build_src_kernel<<<(BB * HINIT * HINIT + 255) / 256, 256>>>(idx);
    wsplit_all<<<dim3(32, 32, 6), dim3(32, 32)>>>(q_w, sr_w, kv_w, proj_w, fc1_w, fc2_w);

    // 1. xn = LN(x), + bf16 splits
    ln256_kernel<1, 1><<<BN, 256>>>(x, xn, n1w, n1b);
    // 2. q = xn @ q_w + q_b
    tc_gemm<0, 0><<<dim3(CC / 128, BN / 128), 256, DSM>>>(ah, al, wh + OFF_Q, wl + OFF_Q, q_b, nullptr, q, BN, CC, CC, nullptr);
    // 3. token2map(tmp) -> kv_map + conf (fused 2x2 pool)
    t2m_tmp_kernel<<<BM, 256>>>(xn, tscore, idx);
    // 4+5. kvconv = im2col(kv_map) @ sr_w + sr_b (gather fused)
    tc_gemm<0, 1><<<dim3(CC / 128, BM / 128), 256, DSM>>>(nullptr, nullptr, wh + OFF_SR, wl + OFF_SR, sr_b, nullptr, kvcv, BM, 1024, CC, kvmap);
    // 6. kvln = LN(kvconv) -> splits only
    ln256_kernel<0, 1><<<BM, 256>>>(kvcv, nullptr, srn_w, srn_b);
    // 7. kv2 = kvln @ kv_w + kv_b
    tc_gemm<0, 0><<<dim3(512 / 128, BM / 128), 256, DSM>>>(ah, al, wh + OFF_KV, wl + OFF_KV, kv_b, nullptr, kv2, BM, CC, 512, nullptr);
    // 8. attention -> splits of a
    attn_kernel<<<dim3(BB * HEADS, (NTOK + 127) / 128), 128>>>(q, kv2, conf);
    // 9. x2 = x + a @ proj_w + proj_b
    tc_gemm<1, 0><<<dim3(CC / 128, BN / 128), 256, DSM>>>(ah, al, wh + OFF_PJ, wl + OFF_PJ, proj_b, x, x2, BN, CC, CC, nullptr);
    // 10. ln2 = LN(x2) -> splits only
    ln256_kernel<0, 1><<<BN, 256>>>(x2, nullptr, n2w, n2b);
    // 11. h = ln2 @ fc1_w + fc1_b
    tc_gemm<0, 0><<<dim3(HID / 128, BN / 128), 256, DSM>>>(ah, al, wh + OFF_F1, wl + OFF_F1, fc1_b, nullptr, h, BN, CC, HID, nullptr);
    // 12. hmap = token2map(h)
    t2m_h_kernel<<<BHW, 256>>>(h, idx);
    // 13. dw = depthwise3x3(hmap), tiled smem
    dwconv_tiled<<<dim3(49, 8, BB), 256, 51200>>>(dw_w, dw_b);
    // 14. hc = gelu(h*skip + gather(dw)/(cnt+eps)) -> splits
    hc_gather_kernel<<<BN, 256>>>(skip_w);
    // 15. out = x2 + hc @ fc2_w + fc2_b
    tc_gemm<1, 0><<<dim3(CC / 128, BN / 128), 256, DSM>>>(ah, al, wh + OFF_F2, wl + OFF_F2, fc2_b, x2, out, BN, HID, CC, nullptr);
}

// round 16
// speedup vs baseline: 1.0277x; 1.0277x over previous
#include <cuda_runtime.h>
#include <cuda_bf16.h>
#include <math.h>
#include <stdint.h>

// ---------------- problem constants ----------------
#define BB      8
#define NTOK    1568
#define CC      256
#define HID     1024
#define HH      56
#define HWSZ    (HH*HH)        // 3136
#define MKV     784            // 28*28
#define HEADS   8
#define DH      32
#define HINIT   112
#define BN      (BB*NTOK)      // 12544
#define BHW     (BB*HWSZ)      // 25088
#define BM      (BB*MKV)       // 6272
#define W4      (1.0f/(4.0f+1e-6f))
#define LN_EPS  1e-5f
#define EPS_C   1e-6f
#define CAP     64

// weight split buffer offsets (elements)
#define OFF_Q   0
#define OFF_SR  65536
#define OFF_KV  327680
#define OFF_PJ  458752
#define OFF_F1  524288
#define OFF_F2  786432
#define WTOT    1048576

typedef unsigned long long u64;

// ---------------- scratch (device globals) ----------------
__device__ float g_xn   [BN*CC];
__device__ float g_q    [BN*CC];
__device__ float g_kvmap[BHW*CC];
__device__ float g_conf [BM];
__device__ float g_kvcv [BM*CC];
__device__ float g_kv2  [BM*2*CC];
__device__ float g_x2   [BN*CC];
__device__ float g_h    [BN*HID];
__device__ float g_hmap [BHW*HID];
__device__ float g_dw   [BHW*HID];
__device__ int   g_tcnt [BN];
__device__ int   g_tsrc [BN*CAP];
__device__ __nv_bfloat16 g_ah [BN*HID];
__device__ __nv_bfloat16 g_al [BN*HID];
__device__ __nv_bfloat16 g_wh [WTOT];
__device__ __nv_bfloat16 g_wl [WTOT];

// ---------------- f32x2 packed-math helpers ----------------
__device__ __forceinline__ u64 pack2(float lo, float hi) {
    u64 r; asm("mov.b64 %0, {%1, %2};" : "=l"(r) : "f"(lo), "f"(hi)); return r;
}
__device__ __forceinline__ u64 pack2s(float v) { return pack2(v, v); }
__device__ __forceinline__ void unpack2(u64 p, float& lo, float& hi) {
    asm("mov.b64 {%0, %1}, %2;" : "=f"(lo), "=f"(hi) : "l"(p));
}
__device__ __forceinline__ u64 fma2(u64 a, u64 b, u64 c) {
    u64 d; asm("fma.rn.f32x2 %0, %1, %2, %3;" : "=l"(d) : "l"(a), "l"(b), "l"(c)); return d;
}

__device__ __forceinline__ float warp_sum(float v) {
#pragma unroll
    for (int o = 16; o > 0; o >>= 1) v += __shfl_down_sync(0xffffffffu, v, o);
    return v;
}

__device__ __forceinline__ void split_bf(float v, __nv_bfloat16& hi, __nv_bfloat16& lo) {
    hi = __float2bfloat16(v);
    lo = __float2bfloat16(v - __bfloat162float(hi));
}

// ---------------- mma.sync / cp.async helpers ----------------
__device__ __forceinline__ uint32_t s2u(const void* p) {
    uint32_t a;
    asm("{ .reg .u64 t; cvta.to.shared.u64 t, %1; cvt.u32.u64 %0, t; }" : "=r"(a) : "l"(p));
    return a;
}
__device__ __forceinline__ void ldsm4(uint32_t* r, uint32_t addr) {
    asm volatile("ldmatrix.sync.aligned.m8n8.x4.shared.b16 {%0,%1,%2,%3}, [%4];"
                 : "=r"(r[0]), "=r"(r[1]), "=r"(r[2]), "=r"(r[3]) : "r"(addr));
}
__device__ __forceinline__ void mma_bf16(float* d, const uint32_t* a, const uint32_t* b) {
    asm volatile("mma.sync.aligned.m16n8k16.row.col.f32.bf16.bf16.f32 "
                 "{%0,%1,%2,%3}, {%4,%5,%6,%7}, {%8,%9}, {%0,%1,%2,%3};"
                 : "+f"(d[0]), "+f"(d[1]), "+f"(d[2]), "+f"(d[3])
                 : "r"(a[0]), "r"(a[1]), "r"(a[2]), "r"(a[3]), "r"(b[0]), "r"(b[1]));
}
__device__ __forceinline__ void cp16(uint32_t dst, const void* src) {
    asm volatile("cp.async.cg.shared.global [%0], [%1], 16;" :: "r"(dst), "l"(src));
}
__device__ __forceinline__ void cp_commit() { asm volatile("cp.async.commit_group;" ::: "memory"); }
__device__ __forceinline__ void cp_wait1()  { asm volatile("cp.async.wait_group 1;"  ::: "memory"); }
__device__ __forceinline__ void cp_wait0()  { asm volatile("cp.async.wait_group 0;"  ::: "memory"); }

// ---------------- tensor-core split-bf16 GEMM (double-buffered cp.async) ----------
#define RS  80
#define STG (4*128*RS)
template<int EPI, int GATHER>
__global__ void __launch_bounds__(256, 2)
tc_gemm(const __nv_bfloat16* __restrict__ Ah, const __nv_bfloat16* __restrict__ Al,
        const __nv_bfloat16* __restrict__ Wh, const __nv_bfloat16* __restrict__ Wl,
        const float* __restrict__ bias, const float* __restrict__ res,
        float* __restrict__ out, int M, int K, int Nc, const float* __restrict__ gsrc) {
    extern __shared__ __align__(16) char sm[];
    const int O_AL = 128 * RS, O_BH = 2 * 128 * RS, O_BL = 3 * 128 * RS;

    int tid = threadIdx.x, wid = tid >> 5, lane = tid & 31;
    int mw = wid >> 1, wc = wid & 1;
    long row0 = (long)blockIdx.y * 128, col0 = (long)blockIdx.x * 128;

    uint32_t sb = s2u(sm);
    int q = lane >> 3, l7 = lane & 7;
    int a_row = mw * 32 + ((q & 1) << 3) + l7;
    int a_kb  = (q >> 1) << 3;
    int b_row = wc * 64 + ((q >> 1) << 3) + l7;
    int b_kb  = (q & 1) << 3;

    float4 pref[2][2];

    auto issueB = [&](int ch, int st) {
        char* base = sm + st * STG;
        long k0 = (long)ch << 5;
#pragma unroll
        for (int it = 0; it < 2; it++) {
            int slot = tid + it * 256, r = slot >> 2, u = slot & 3;
            int so = r * RS + u * 16;
            long gb = (col0 + r) * K + k0 + u * 8;
            cp16(s2u(base + O_BH + so), Wh + gb);
            cp16(s2u(base + O_BL + so), Wl + gb);
        }
    };
    auto issueA = [&](int ch, int st) {
        char* base = sm + st * STG;
        long k0 = (long)ch << 5;
#pragma unroll
        for (int it = 0; it < 2; it++) {
            int slot = tid + it * 256, r = slot >> 2, u = slot & 3;
            int so = r * RS + u * 16;
            long ga = (row0 + r) * K + k0 + u * 8;
            cp16(s2u(base + so), Ah + ga);
            cp16(s2u(base + O_AL + so), Al + ga);
        }
    };
    auto prefA = [&](int ch) {
        long k0 = (long)ch << 5;
#pragma unroll
        for (int it = 0; it < 2; it++) {
            int slot = tid + it * 256, r = slot >> 2, u = slot & 3;
            long row = row0 + r;
            int kg = (int)k0 + u * 8;
            int b = (int)(row / MKV), m = (int)(row - (long)b * MKV);
            int r2 = m / 28, c2 = m - r2 * 28;
            int di = kg >> 9, dj = (kg >> 8) & 1, ci = kg & 255;
            const float* src = gsrc + (((size_t)b * HWSZ) + (2 * r2 + di) * HH + (2 * c2 + dj)) * CC + ci;
            pref[it][0] = *(const float4*)src;
            pref[it][1] = *(const float4*)(src + 4);
        }
    };
    auto storeA = [&](int st) {
        char* base = sm + st * STG;
#pragma unroll
        for (int it = 0; it < 2; it++) {
            int slot = tid + it * 256, r = slot >> 2, u = slot & 3;
            int so = r * RS + u * 16;
            float f[8] = {pref[it][0].x, pref[it][0].y, pref[it][0].z, pref[it][0].w,
                          pref[it][1].x, pref[it][1].y, pref[it][1].z, pref[it][1].w};
            __align__(16) __nv_bfloat16 hb[8], lb[8];
#pragma unroll
            for (int e = 0; e < 8; e++) split_bf(f[e], hb[e], lb[e]);
            *(uint4*)(base + so)        = *(uint4*)hb;
            *(uint4*)(base + O_AL + so) = *(uint4*)lb;
        }
    };

    float acc[2][8][4];
#pragma unroll
    for (int i = 0; i < 2; i++)
#pragma unroll
        for (int j = 0; j < 8; j++)
#pragma unroll
            for (int k = 0; k < 4; k++) acc[i][j][k] = 0.f;

    int nch = K >> 5;
    if (GATHER) prefA(0); else issueA(0, 0);
    issueB(0, 0);
    cp_commit();

    for (int ch = 0; ch < nch; ch++) {
        int s = ch & 1;
        if (GATHER) storeA(s);
        if (ch + 1 < nch) {
            if (!GATHER) issueA(ch + 1, s ^ 1);
            issueB(ch + 1, s ^ 1);
            cp_commit();
            if (GATHER) prefA(ch + 1);
            cp_wait1();
        } else {
            cp_wait0();
        }
        __syncthreads();

        uint32_t sbase = sb + s * STG;
#pragma unroll
        for (int ks = 0; ks < 2; ks++) {
            uint32_t ahf[2][4], alf[2][4];
#pragma unroll
            for (int mi = 0; mi < 2; mi++) {
                uint32_t ao = (uint32_t)((a_row + mi * 16) * RS + (ks * 16 + a_kb) * 2);
                ldsm4(ahf[mi], sbase + ao);
                ldsm4(alf[mi], sbase + O_AL + ao);
            }
#pragma unroll
            for (int ng = 0; ng < 4; ng++) {
                uint32_t bh[4], bl[4];
                uint32_t bo = (uint32_t)((b_row + ng * 16) * RS + (ks * 16 + b_kb) * 2);
                ldsm4(bh, sbase + O_BH + bo);
                ldsm4(bl, sbase + O_BL + bo);
#pragma unroll
                for (int mi = 0; mi < 2; mi++) {
                    mma_bf16(acc[mi][ng * 2],     ahf[mi], bh);
                    mma_bf16(acc[mi][ng * 2 + 1], ahf[mi], bh + 2);
                    mma_bf16(acc[mi][ng * 2],     ahf[mi], bl);
                    mma_bf16(acc[mi][ng * 2 + 1], ahf[mi], bl + 2);
                    mma_bf16(acc[mi][ng * 2],     alf[mi], bh);
                    mma_bf16(acc[mi][ng * 2 + 1], alf[mi], bh + 2);
                }
            }
        }
        __syncthreads();
    }

    int r_lane = lane >> 2, c_lane = (lane & 3) << 1;
#pragma unroll
    for (int mi = 0; mi < 2; mi++) {
#pragma unroll
        for (int ni = 0; ni < 8; ni++) {
            long r = row0 + mw * 32 + mi * 16 + r_lane;
            long c = col0 + wc * 64 + ni * 8 + c_lane;
            float b0 = bias[c], b1 = bias[c + 1];
            float2 v0 = {acc[mi][ni][0] + b0, acc[mi][ni][1] + b1};
            float2 v1 = {acc[mi][ni][2] + b0, acc[mi][ni][3] + b1};
            if (EPI == 1) {
                float2 r0 = *(const float2*)(res + r * Nc + c);
                float2 r1 = *(const float2*)(res + (r + 8) * Nc + c);
                v0.x += r0.x; v0.y += r0.y;
                v1.x += r1.x; v1.y += r1.y;
            }
            *(float2*)(out + r * Nc + c) = v0;
            *(float2*)(out + (r + 8) * Nc + c) = v1;
        }
    }
}

// ---------------- batched weight transpose+split: exact grid, 1024 real blocks ------
// cum block counts: q 64 | sr 256 | kv 128 | pj 64 | f1 256 | f2 256  (nbx = N/32)
__global__ void wsplit_all(const float* __restrict__ q_w,  const float* __restrict__ sr_w,
                           const float* __restrict__ kv_w, const float* __restrict__ proj_w,
                           const float* __restrict__ fc1_w,const float* __restrict__ fc2_w) {
    int bid = blockIdx.x;
    const float* W; int K, N, nbx; size_t off; int lid;
    if (bid < 64)        { W = q_w;    K = 256;  N = 256;  off = OFF_Q;  lid = bid;        nbx = 8;  }
    else if (bid < 320)  { W = sr_w;   K = 1024; N = 256;  off = OFF_SR; lid = bid - 64;   nbx = 8;  }
    else if (bid < 448)  { W = kv_w;   K = 256;  N = 512;  off = OFF_KV; lid = bid - 320;  nbx = 16; }
    else if (bid < 512)  { W = proj_w; K = 256;  N = 256;  off = OFF_PJ; lid = bid - 448;  nbx = 8;  }
    else if (bid < 768)  { W = fc1_w;  K = 256;  N = 1024; off = OFF_F1; lid = bid - 512;  nbx = 32; }
    else                 { W = fc2_w;  K = 1024; N = 256;  off = OFF_F2; lid = bid - 768;  nbx = 8;  }
    int nb = (lid % nbx) * 32, kb = (lid / nbx) * 32;
    __shared__ float t[32][33];
    int tx = threadIdx.x, ty = threadIdx.y;
    t[ty][tx] = W[(size_t)(kb + ty) * N + nb + tx];
    __syncthreads();
    float v = t[tx][ty];
    __nv_bfloat16 hi, lo;
    split_bf(v, hi, lo);
    size_t o = off + (size_t)(nb + ty) * K + kb + tx;
    g_wh[o] = hi;
    g_wl[o] = lo;
}

// ---------------- LayerNorm, warp-per-row (8 rows / 256-thread block) ----------------
template<int WF32, int WSPL>
__global__ void ln256_kernel(const float* __restrict__ in, float* __restrict__ out,
                             const float* __restrict__ w, const float* __restrict__ b) {
    int warp = threadIdx.x >> 5, lane = threadIdx.x & 31;
    long row = (long)blockIdx.x * 8 + warp;
    const float4* ip = (const float4*)(in + row * CC);
    float4 v0 = ip[lane * 2], v1 = ip[lane * 2 + 1];
    float s = v0.x + v0.y + v0.z + v0.w + v1.x + v1.y + v1.z + v1.w;
    s = warp_sum(s);
    float mean = __shfl_sync(0xffffffffu, s, 0) * (1.0f / CC);
    float c0[8] = {v0.x - mean, v0.y - mean, v0.z - mean, v0.w - mean,
                   v1.x - mean, v1.y - mean, v1.z - mean, v1.w - mean};
    float s2 = 0.f;
#pragma unroll
    for (int e = 0; e < 8; e++) s2 += c0[e] * c0[e];
    s2 = warp_sum(s2);
    float rstd = rsqrtf(__shfl_sync(0xffffffffu, s2, 0) * (1.0f / CC) + LN_EPS);
    const float4* wp = (const float4*)(w) + lane * 2;
    const float4* bp = (const float4*)(b) + lane * 2;
    float4 w0 = wp[0], w1 = wp[1], b0 = bp[0], b1 = bp[1];
    float o[8];
    o[0] = c0[0] * rstd * w0.x + b0.x;  o[1] = c0[1] * rstd * w0.y + b0.y;
    o[2] = c0[2] * rstd * w0.z + b0.z;  o[3] = c0[3] * rstd * w0.w + b0.w;
    o[4] = c0[4] * rstd * w1.x + b1.x;  o[5] = c0[5] * rstd * w1.y + b1.y;
    o[6] = c0[6] * rstd * w1.z + b1.z;  o[7] = c0[7] * rstd * w1.w + b1.w;
    size_t g = (size_t)row * CC + lane * 8;
    if (WF32) {
        float4 q0 = {o[0], o[1], o[2], o[3]}, q1 = {o[4], o[5], o[6], o[7]};
        *(float4*)(out + g) = q0;
        *(float4*)(out + g + 4) = q1;
    }
    if (WSPL) {
        __align__(16) __nv_bfloat16 hb[8], lb[8];
#pragma unroll
        for (int e = 0; e < 8; e++) split_bf(o[e], hb[e], lb[e]);
        *(uint4*)(g_ah + g) = *(uint4*)hb;
        *(uint4*)(g_al + g) = *(uint4*)lb;
    }
}

// ---------------- token2map tmp + fused conf: one 2x2 pixel block per CTA ----------
__global__ void t2m_tmp_kernel(const float* __restrict__ xn, const float* __restrict__ tscore,
                               const int* __restrict__ idx) {
    int g = blockIdx.x;                   // b*MKV + m  (2x2 block id)
    int b = g / MKV, m = g - b * MKV;
    int r2 = m / 28, c2 = m - r2 * 28;
    int p = threadIdx.x >> 6;             // 0..3 : (dy,dx)
    int dy = p >> 1, dx = p & 1;
    int t = threadIdx.x & 63;
    int hw = (2 * r2 + dy) * HH + 2 * c2 + dx;
    int gi = (2 * (2 * r2 + dy)) * HINIT + 2 * (2 * c2 + dx);
    const int* ib = idx + (size_t)b * (HINIT * HINIT);
    int t0 = ib[gi], t1 = ib[gi + 1], t2 = ib[gi + HINIT], t3 = ib[gi + HINIT + 1];
    const float4* x0 = (const float4*)(xn + ((size_t)b * NTOK + t0) * CC);
    const float4* x1 = (const float4*)(xn + ((size_t)b * NTOK + t1) * CC);
    const float4* x2 = (const float4*)(xn + ((size_t)b * NTOK + t2) * CC);
    const float4* x3 = (const float4*)(xn + ((size_t)b * NTOK + t3) * CC);
    float4 a = x0[t], b4 = x1[t], c4 = x2[t], d4 = x3[t];
    float4 o;
    o.x = W4 * (a.x + b4.x + c4.x + d4.x);
    o.y = W4 * (a.y + b4.y + c4.y + d4.y);
    o.z = W4 * (a.z + b4.z + c4.z + d4.z);
    o.w = W4 * (a.w + b4.w + c4.w + d4.w);
    ((float4*)(g_kvmap + ((size_t)b * HWSZ + hw) * CC))[t] = o;
    __shared__ float cf[4];
    if (t == 0) {
        const float* ts = tscore + (size_t)b * NTOK;
        cf[p] = W4 * (ts[t0] + ts[t1] + ts[t2] + ts[t3]);
    }
    __syncthreads();
    if (threadIdx.x == 0)
        g_conf[g] = 0.25f * (cf[0] + cf[1] + cf[2] + cf[3]);
}

// ---------------- fused attention: branchy online softmax, f32x2, 256 thr ----------
__global__ void attn_kernel(const float* __restrict__ q, const float* __restrict__ kv2,
                            const float* __restrict__ conf) {
    const int KT = 112;
    const int DP = DH / 2;
    int bh = blockIdx.x;
    int b = bh / HEADS, h = bh - b * HEADS;
    int n = blockIdx.y * 256 + threadIdx.x;
    bool valid = n < NTOK;
    __shared__ float ksh[KT][DH];
    __shared__ float vsh[KT][DH];
    __shared__ float csh[KT];
    const float scale = 0.17677669529663687f;
    u64 q2[DP], oa2[DP];
#pragma unroll
    for (int k = 0; k < DP; k++) { q2[k] = 0ull; oa2[k] = 0ull; }
    if (valid) {
        const float* qp = q + ((size_t)b * NTOK + n) * CC + h * DH;
#pragma unroll
        for (int k = 0; k < DP; k++) q2[k] = pack2(qp[2 * k] * scale, qp[2 * k + 1] * scale);
    }
    float mrun = -1e30f, lrun = 0.f;
    for (int t = 0; t < 7; t++) {
        int m0 = t * KT;
        __syncthreads();
        for (int i = threadIdx.x; i < KT * DH; i += 256) {
            int mm = i / DH, dd = i - mm * DH;
            size_t base = ((size_t)b * MKV + m0 + mm) * (2 * CC) + h * DH + dd;
            ksh[mm][dd] = kv2[base];
            vsh[mm][dd] = kv2[base + CC];
        }
        if (threadIdx.x < KT) csh[threadIdx.x] = conf[(size_t)b * MKV + m0 + threadIdx.x];
        __syncthreads();
        for (int j = 0; j < KT; j++) {
            const u64* kp = (const u64*)&ksh[j][0];
            u64 s2 = 0ull;
#pragma unroll
            for (int k = 0; k < DP; k++) s2 = fma2(q2[k], kp[k], s2);
            float slo, shi;
            unpack2(s2, slo, shi);
            float s = slo + shi + csh[j];
            const u64* vp = (const u64*)&vsh[j][0];
            if (s <= mrun) {
                float p = __expf(s - mrun);
                lrun += p;
                u64 p2 = pack2s(p);
#pragma unroll
                for (int k = 0; k < DP; k++) oa2[k] = fma2(p2, vp[k], oa2[k]);
            } else {
                float corr = __expf(mrun - s);
                lrun = lrun * corr + 1.0f;
                u64 corr2 = pack2s(corr);
#pragma unroll
                for (int k = 0; k < DP; k++) oa2[k] = fma2(oa2[k], corr2, vp[k]);
                mrun = s;
            }
        }
    }
    if (valid) {
        float inv = 1.0f / lrun;
        size_t op = ((size_t)b * NTOK + n) * CC + h * DH;
#pragma unroll
        for (int k = 0; k < DP; k++) {
            float lo, hi;
            unpack2(oa2[k], lo, hi);
            __nv_bfloat16 h0, l0, h1, l1;
            split_bf(lo * inv, h0, l0);
            split_bf(hi * inv, h1, l1);
            g_ah[op + 2 * k] = h0;  g_al[op + 2 * k] = l0;
            g_ah[op + 2 * k + 1] = h1;  g_al[op + 2 * k + 1] = l1;
        }
    }
}

// ---------------- token2map for h (1024 ch), float4 ----------------
__global__ void t2m_h_kernel(const float* __restrict__ hin, const int* __restrict__ idx) {
    int blk = blockIdx.x;
    int b = blk / HWSZ, hw = blk - b * HWSZ;
    int r = hw / HH, c = hw - r * HH;
    int gi = (2 * r) * HINIT + 2 * c;
    const int* ib = idx + (size_t)b * (HINIT * HINIT);
    int t0 = ib[gi], t1 = ib[gi + 1], t2 = ib[gi + HINIT], t3 = ib[gi + HINIT + 1];
    const float4* x0 = (const float4*)(hin + ((size_t)b * NTOK + t0) * HID);
    const float4* x1 = (const float4*)(hin + ((size_t)b * NTOK + t1) * HID);
    const float4* x2 = (const float4*)(hin + ((size_t)b * NTOK + t2) * HID);
    const float4* x3 = (const float4*)(hin + ((size_t)b * NTOK + t3) * HID);
    float4* o = (float4*)(g_hmap + (size_t)blk * HID);
    int t = threadIdx.x;
    float4 a = x0[t], b4 = x1[t], c4 = x2[t], d4 = x3[t];
    float4 v;
    v.x = W4 * (a.x + b4.x + c4.x + d4.x);
    v.y = W4 * (a.y + b4.y + c4.y + d4.y);
    v.z = W4 * (a.z + b4.z + c4.z + d4.z);
    v.w = W4 * (a.w + b4.w + c4.w + d4.w);
    o[t] = v;
}

// ---------------- tiled depthwise 3x3: 8x8 spatial x 128ch, smem halo reuse -------
__global__ void dwconv_tiled(const float* __restrict__ dww, const float* __restrict__ dwb) {
    extern __shared__ float4 sh[];   // [100][32]
    int tile = blockIdx.x, slice = blockIdx.y, b = blockIdx.z;
    int ty0 = (tile / 7) * 8, tx0 = (tile % 7) * 8;
    const float4* hb = (const float4*)(g_hmap + (size_t)b * HWSZ * HID);
    for (int i = threadIdx.x; i < 3200; i += 256) {
        int px = i >> 5, cl = i & 31;
        int hy = ty0 + (px / 10) - 1, hx = tx0 + (px % 10) - 1;
        float4 v = {0.f, 0.f, 0.f, 0.f};
        if (hy >= 0 && hy < HH && hx >= 0 && hx < HH)
            v = hb[(size_t)(hy * HH + hx) * 256 + slice * 32 + cl];
        sh[px * 32 + cl] = v;
    }
    __syncthreads();
    int cl = threadIdx.x & 31;
    int pr = threadIdx.x >> 5;
    int cg = slice * 32 + cl;
    float4 wreg[9];
#pragma unroll
    for (int j = 0; j < 9; j++) wreg[j] = ((const float4*)dww)[j * 256 + cg];
    float4 bias = ((const float4*)dwb)[cg];
    float4* ob = (float4*)(g_dw + (size_t)b * HWSZ * HID);
#pragma unroll
    for (int pc = 0; pc < 8; pc++) {
        float4 acc = bias;
#pragma unroll
        for (int ky = 0; ky < 3; ky++)
#pragma unroll
            for (int kx = 0; kx < 3; kx++) {
                float4 in = sh[((pr + ky) * 10 + pc + kx) * 32 + cl];
                float4 w = wreg[ky * 3 + kx];
                acc.x = fmaf(in.x, w.x, acc.x);
                acc.y = fmaf(in.y, w.y, acc.y);
                acc.z = fmaf(in.z, w.z, acc.z);
                acc.w = fmaf(in.w, w.w, acc.w);
            }
        ob[(size_t)((ty0 + pr) * HH + tx0 + pc) * 256 + cg] = acc;
    }
}

// ---------------- map2token: token source lists ----------------
__global__ void fillint0_kernel(int* p, int n) {
    int g = blockIdx.x * blockDim.x + threadIdx.x;
    if (g < n) p[g] = 0;
}

__global__ void build_src_kernel(const int* __restrict__ idx) {
    int g = blockIdx.x * blockDim.x + threadIdx.x;
    if (g >= BB * HINIT * HINIT) return;
    int b = g / (HINIT * HINIT), i = g - b * (HINIT * HINIT);
    int tok = idx[(size_t)b * HINIT * HINIT + i];
    int ir = i / HINIT, ic = i - ir * HINIT;
    int hw = (ir >> 1) * HH + (ic >> 1);
    int row = b * NTOK + tok;
    int slot = atomicAdd(&g_tcnt[row], 1);
    if (slot < CAP) g_tsrc[row * CAP + slot] = hw;
}

__global__ void hc_gather_kernel(const float* __restrict__ skipw) {
    int row = blockIdx.x;
    int b = row / NTOK;
    int c4 = threadIdx.x;
    int cnt = g_tcnt[row];
    const float4* dwb = (const float4*)(g_dw + (size_t)b * HWSZ * HID);
    float4 acc = {0.f, 0.f, 0.f, 0.f};
    for (int s = 0; s < cnt; s++) {
        int hw = g_tsrc[row * CAP + s];
        float4 v = dwb[(size_t)hw * 256 + c4];
        acc.x += v.x; acc.y += v.y; acc.z += v.z; acc.w += v.w;
    }
    float inv = 1.0f / ((float)cnt + EPS_C);
    float4 hv = ((const float4*)g_h)[(size_t)row * 256 + c4];
    float4 sw = ((const float4*)skipw)[c4];
    float v[4];
    v[0] = hv.x * sw.x + acc.x * inv;
    v[1] = hv.y * sw.y + acc.y * inv;
    v[2] = hv.z * sw.z + acc.z * inv;
    v[3] = hv.w * sw.w + acc.w * inv;
    __align__(8) __nv_bfloat16 hb[4], lb[4];
#pragma unroll
    for (int e = 0; e < 4; e++) {
        float gv = 0.5f * v[e] * (1.0f + erff(v[e] * 0.70710678118654752f));
        split_bf(gv, hb[e], lb[e]);
    }
    size_t o = (size_t)row * HID + c4 * 4;
    *(uint2*)(g_ah + o) = *(uint2*)hb;
    *(uint2*)(g_al + o) = *(uint2*)lb;
}

// ---------------- launch ----------------
extern "C" void kernel_launch(void* const* d_in, const int* in_sizes, int n_in,
                              void* d_out, int out_size) {
    const float* x       = (const float*)d_in[0];
    const float* tscore  = (const float*)d_in[1];
    const int*   idx     = (const int*)  d_in[2];
    const float* n1w     = (const float*)d_in[3];
    const float* n1b     = (const float*)d_in[4];
    const float* q_w     = (const float*)d_in[5];
    const float* q_b     = (const float*)d_in[6];
    const float* kv_w    = (const float*)d_in[7];
    const float* kv_b    = (const float*)d_in[8];
    const float* sr_w    = (const float*)d_in[9];
    const float* sr_b    = (const float*)d_in[10];
    const float* srn_w   = (const float*)d_in[11];
    const float* srn_b   = (const float*)d_in[12];
    const float* proj_w  = (const float*)d_in[13];
    const float* proj_b  = (const float*)d_in[14];
    const float* n2w     = (const float*)d_in[15];
    const float* n2b     = (const float*)d_in[16];
    const float* fc1_w   = (const float*)d_in[17];
    const float* fc1_b   = (const float*)d_in[18];
    const float* skip_w  = (const float*)d_in[19];
    const float* dw_w    = (const float*)d_in[20];
    const float* dw_b    = (const float*)d_in[21];
    const float* fc2_w   = (const float*)d_in[22];
    const float* fc2_b   = (const float*)d_in[23];
    float* out = (float*)d_out;

    float *xn, *q, *kvcv, *kv2, *x2, *h, *conf, *kvmap;
    int *tcnt;
    __nv_bfloat16 *ah, *al, *wh, *wl;
    cudaGetSymbolAddress((void**)&xn,    g_xn);
    cudaGetSymbolAddress((void**)&q,     g_q);
    cudaGetSymbolAddress((void**)&kvcv,  g_kvcv);
    cudaGetSymbolAddress((void**)&kv2,   g_kv2);
    cudaGetSymbolAddress((void**)&x2,    g_x2);
    cudaGetSymbolAddress((void**)&h,     g_h);
    cudaGetSymbolAddress((void**)&conf,  g_conf);
    cudaGetSymbolAddress((void**)&kvmap, g_kvmap);
    cudaGetSymbolAddress((void**)&tcnt,  g_tcnt);
    cudaGetSymbolAddress((void**)&ah,    g_ah);
    cudaGetSymbolAddress((void**)&al,    g_al);
    cudaGetSymbolAddress((void**)&wh,    g_wh);
    cudaGetSymbolAddress((void**)&wl,    g_wl);

    const int DSM = 2 * STG;   // 81920 B
    cudaFuncSetAttribute(tc_gemm<0, 0>, cudaFuncAttributeMaxDynamicSharedMemorySize, DSM);
    cudaFuncSetAttribute(tc_gemm<1, 0>, cudaFuncAttributeMaxDynamicSharedMemorySize, DSM);
    cudaFuncSetAttribute(tc_gemm<0, 1>, cudaFuncAttributeMaxDynamicSharedMemorySize, DSM);
    cudaFuncSetAttribute(dwconv_tiled, cudaFuncAttributeMaxDynamicSharedMemorySize, 51200);

    // independent prep: token source lists + all weight splits (exact grid)
    fillint0_kernel<<<(BN + 255) / 256, 256>>>(tcnt, BN);
    build_src_kernel<<<(BB * HINIT * HINIT + 255) / 256, 256>>>(idx);
    wsplit_all<<<1024, dim3(32, 32)>>>(q_w, sr_w, kv_w, proj_w, fc1_w, fc2_w);

    // 1. xn = LN(x), + bf16 splits
    ln256_kernel<1, 1><<<BN / 8, 256>>>(x, xn, n1w, n1b);
    // 2. q = xn @ q_w + q_b
    tc_gemm<0, 0><<<dim3(CC / 128, BN / 128), 256, DSM>>>(ah, al, wh + OFF_Q, wl + OFF_Q, q_b, nullptr, q, BN, CC, CC, nullptr);
    // 3. token2map(tmp) -> kv_map + conf (fused 2x2 pool)
    t2m_tmp_kernel<<<BM, 256>>>(xn, tscore, idx);
    // 4+5. kvconv = im2col(kv_map) @ sr_w + sr_b (gather fused)
    tc_gemm<0, 1><<<dim3(CC / 128, BM / 128), 256, DSM>>>(nullptr, nullptr, wh + OFF_SR, wl + OFF_SR, sr_b, nullptr, kvcv, BM, 1024, CC, kvmap);
    // 6. kvln = LN(kvconv) -> splits only
    ln256_kernel<0, 1><<<BM / 8, 256>>>(kvcv, nullptr, srn_w, srn_b);
    // 7. kv2 = kvln @ kv_w + kv_b
    tc_gemm<0, 0><<<dim3(512 / 128, BM / 128), 256, DSM>>>(ah, al, wh + OFF_KV, wl + OFF_KV, kv_b, nullptr, kv2, BM, CC, 512, nullptr);
    // 8. attention -> splits of a
    attn_kernel<<<dim3(BB * HEADS, (NTOK + 255) / 256), 256>>>(q, kv2, conf);
    // 9. x2 = x + a @ proj_w + proj_b
    tc_gemm<1, 0><<<dim3(CC / 128, BN / 128), 256, DSM>>>(ah, al, wh + OFF_PJ, wl + OFF_PJ, proj_b, x, x2, BN, CC, CC, nullptr);
    // 10. ln2 = LN(x2) -> splits only
    ln256_kernel<0, 1><<<BN / 8, 256>>>(x2, nullptr, n2w, n2b);
    // 11. h = ln2 @ fc1_w + fc1_b
    tc_gemm<0, 0><<<dim3(HID / 128, BN / 128), 256, DSM>>>(ah, al, wh + OFF_F1, wl + OFF_F1, fc1_b, nullptr, h, BN, CC, HID, nullptr);
    // 12. hmap = token2map(h)
    t2m_h_kernel<<<BHW, 256>>>(h, idx);
    // 13. dw = depthwise3x3(hmap), tiled smem
    dwconv_tiled<<<dim3(49, 8, BB), 256, 51200>>>(dw_w, dw_b);
    // 14. hc = gelu(h*skip + gather(dw)/(cnt+eps)) -> splits
    hc_gather_kernel<<<BN, 256>>>(skip_w);
    // 15. out = x2 + hc @ fc2_w + fc2_b
    tc_gemm<1, 0><<<dim3(CC / 128, BN / 128), 256, DSM>>>(ah, al, wh + OFF_F2, wl + OFF_F2, fc2_b, x2, out, BN, HID, CC, nullptr);
}

// round 17
// speedup vs baseline: 1.1508x; 1.1198x over previous
#include <cuda_runtime.h>
#include <cuda_fp16.h>
#include <math.h>
#include <stdint.h>

// ---------------- problem constants ----------------
#define BB      8
#define NTOK    1568
#define CC      256
#define HID     1024
#define HH      56
#define HWSZ    (HH*HH)        // 3136
#define MKV     784            // 28*28
#define HEADS   8
#define DH      32
#define HINIT   112
#define BN      (BB*NTOK)      // 12544
#define BHW     (BB*HWSZ)      // 25088
#define BM      (BB*MKV)       // 6272
#define W4      (1.0f/(4.0f+1e-6f))
#define LN_EPS  1e-5f
#define EPS_C   1e-6f
#define CAP     64

// weight buffer offsets (elements)
#define OFF_Q   0
#define OFF_SR  65536
#define OFF_KV  327680
#define OFF_PJ  458752
#define OFF_F1  524288
#define OFF_F2  786432
#define WTOT    1048576

typedef unsigned long long u64;

// ---------------- scratch (device globals) ----------------
__device__ float g_xn   [BN*CC];
__device__ float g_q    [BN*CC];
__device__ float g_kvmap[BHW*CC];
__device__ float g_conf [BM];
__device__ float g_kvcv [BM*CC];
__device__ float g_kv2  [BM*2*CC];
__device__ float g_x2   [BN*CC];
__device__ float g_h    [BN*HID];
__device__ float g_dw   [BHW*HID];
__device__ int   g_tcnt [BN];
__device__ int   g_tsrc [BN*CAP];
__device__ __half g_ah [BN*HID];
__device__ __half g_al [BN*HID];
__device__ __half g_wh [WTOT];

// ---------------- f32x2 packed-math helpers ----------------
__device__ __forceinline__ u64 pack2(float lo, float hi) {
    u64 r; asm("mov.b64 %0, {%1, %2};" : "=l"(r) : "f"(lo), "f"(hi)); return r;
}
__device__ __forceinline__ u64 pack2s(float v) { return pack2(v, v); }
__device__ __forceinline__ void unpack2(u64 p, float& lo, float& hi) {
    asm("mov.b64 {%0, %1}, %2;" : "=f"(lo), "=f"(hi) : "l"(p));
}
__device__ __forceinline__ u64 fma2(u64 a, u64 b, u64 c) {
    u64 d; asm("fma.rn.f32x2 %0, %1, %2, %3;" : "=l"(d) : "l"(a), "l"(b), "l"(c)); return d;
}

__device__ __forceinline__ float warp_sum(float v) {
#pragma unroll
    for (int o = 16; o > 0; o >>= 1) v += __shfl_down_sync(0xffffffffu, v, o);
    return v;
}

// fp16 split: v = hi + lo exactly to ~2^-22 relative
__device__ __forceinline__ void split_h(float v, __half& hi, __half& lo) {
    hi = __float2half(v);
    lo = __float2half(v - __half2float(hi));
}

// ---------------- mma.sync / cp.async helpers ----------------
__device__ __forceinline__ uint32_t s2u(const void* p) {
    uint32_t a;
    asm("{ .reg .u64 t; cvta.to.shared.u64 t, %1; cvt.u32.u64 %0, t; }" : "=r"(a) : "l"(p));
    return a;
}
__device__ __forceinline__ void ldsm4(uint32_t* r, uint32_t addr) {
    asm volatile("ldmatrix.sync.aligned.m8n8.x4.shared.b16 {%0,%1,%2,%3}, [%4];"
                 : "=r"(r[0]), "=r"(r[1]), "=r"(r[2]), "=r"(r[3]) : "r"(addr));
}
__device__ __forceinline__ void mma_f16(float* d, const uint32_t* a, const uint32_t* b) {
    asm volatile("mma.sync.aligned.m16n8k16.row.col.f32.f16.f16.f32 "
                 "{%0,%1,%2,%3}, {%4,%5,%6,%7}, {%8,%9}, {%0,%1,%2,%3};"
                 : "+f"(d[0]), "+f"(d[1]), "+f"(d[2]), "+f"(d[3])
                 : "r"(a[0]), "r"(a[1]), "r"(a[2]), "r"(a[3]), "r"(b[0]), "r"(b[1]));
}
__device__ __forceinline__ void cp16(uint32_t dst, const void* src) {
    asm volatile("cp.async.cg.shared.global [%0], [%1], 16;" :: "r"(dst), "l"(src));
}
__device__ __forceinline__ void cp_commit() { asm volatile("cp.async.commit_group;" ::: "memory"); }
__device__ __forceinline__ void cp_wait1()  { asm volatile("cp.async.wait_group 1;"  ::: "memory"); }
__device__ __forceinline__ void cp_wait0()  { asm volatile("cp.async.wait_group 0;"  ::: "memory"); }

// ---------------- tensor-core GEMM: (Ah+Al fp16) @ (Wh fp16)^T, 2 passes -------------
// C[M,N] = A[M,K] @ W^T[N,K] + bias (+res). M,N %128==0, K%32==0.
// GATHER=1: A gathered on the fly from gsrc (kv_map im2col view), split inline.
#define RS  80
#define STG (3*128*RS)   // 30720 bytes per stage (Ah | Al | Bh)
template<int EPI, int GATHER>
__global__ void __launch_bounds__(256, 2)
tc_gemm(const __half* __restrict__ Ah, const __half* __restrict__ Al,
        const __half* __restrict__ Wh,
        const float* __restrict__ bias, const float* __restrict__ res,
        float* __restrict__ out, int M, int K, int Nc, const float* __restrict__ gsrc) {
    extern __shared__ __align__(16) char sm[];
    const int O_AL = 128 * RS, O_BH = 2 * 128 * RS;

    int tid = threadIdx.x, wid = tid >> 5, lane = tid & 31;
    int mw = wid >> 1, wc = wid & 1;
    long row0 = (long)blockIdx.y * 128, col0 = (long)blockIdx.x * 128;

    uint32_t sb = s2u(sm);
    int q = lane >> 3, l7 = lane & 7;
    int a_row = mw * 32 + ((q & 1) << 3) + l7;
    int a_kb  = (q >> 1) << 3;
    int b_row = wc * 64 + ((q >> 1) << 3) + l7;
    int b_kb  = (q & 1) << 3;

    float4 pref[2][2];

    auto issueB = [&](int ch, int st) {
        char* base = sm + st * STG;
        long k0 = (long)ch << 5;
#pragma unroll
        for (int it = 0; it < 2; it++) {
            int slot = tid + it * 256, r = slot >> 2, u = slot & 3;
            int so = r * RS + u * 16;
            long gb = (col0 + r) * K + k0 + u * 8;
            cp16(s2u(base + O_BH + so), Wh + gb);
        }
    };
    auto issueA = [&](int ch, int st) {
        char* base = sm + st * STG;
        long k0 = (long)ch << 5;
#pragma unroll
        for (int it = 0; it < 2; it++) {
            int slot = tid + it * 256, r = slot >> 2, u = slot & 3;
            int so = r * RS + u * 16;
            long ga = (row0 + r) * K + k0 + u * 8;
            cp16(s2u(base + so), Ah + ga);
            cp16(s2u(base + O_AL + so), Al + ga);
        }
    };
    auto prefA = [&](int ch) {
        long k0 = (long)ch << 5;
#pragma unroll
        for (int it = 0; it < 2; it++) {
            int slot = tid + it * 256, r = slot >> 2, u = slot & 3;
            long row = row0 + r;
            int kg = (int)k0 + u * 8;
            int b = (int)(row / MKV), m = (int)(row - (long)b * MKV);
            int r2 = m / 28, c2 = m - r2 * 28;
            int di = kg >> 9, dj = (kg >> 8) & 1, ci = kg & 255;
            const float* src = gsrc + (((size_t)b * HWSZ) + (2 * r2 + di) * HH + (2 * c2 + dj)) * CC + ci;
            pref[it][0] = *(const float4*)src;
            pref[it][1] = *(const float4*)(src + 4);
        }
    };
    auto storeA = [&](int st) {
        char* base = sm + st * STG;
#pragma unroll
        for (int it = 0; it < 2; it++) {
            int slot = tid + it * 256, r = slot >> 2, u = slot & 3;
            int so = r * RS + u * 16;
            float f[8] = {pref[it][0].x, pref[it][0].y, pref[it][0].z, pref[it][0].w,
                          pref[it][1].x, pref[it][1].y, pref[it][1].z, pref[it][1].w};
            __align__(16) __half hb[8], lb[8];
#pragma unroll
            for (int e = 0; e < 8; e++) split_h(f[e], hb[e], lb[e]);
            *(uint4*)(base + so)        = *(uint4*)hb;
            *(uint4*)(base + O_AL + so) = *(uint4*)lb;
        }
    };

    float acc[2][8][4];
#pragma unroll
    for (int i = 0; i < 2; i++)
#pragma unroll
        for (int j = 0; j < 8; j++)
#pragma unroll
            for (int k = 0; k < 4; k++) acc[i][j][k] = 0.f;

    int nch = K >> 5;
    if (GATHER) prefA(0); else issueA(0, 0);
    issueB(0, 0);
    cp_commit();

    for (int ch = 0; ch < nch; ch++) {
        int s = ch & 1;
        if (GATHER) storeA(s);
        if (ch + 1 < nch) {
            if (!GATHER) issueA(ch + 1, s ^ 1);
            issueB(ch + 1, s ^ 1);
            cp_commit();
            if (GATHER) prefA(ch + 1);
            cp_wait1();
        } else {
            cp_wait0();
        }
        __syncthreads();

        uint32_t sbase = sb + s * STG;
#pragma unroll
        for (int ks = 0; ks < 2; ks++) {
            uint32_t ahf[2][4], alf[2][4];
#pragma unroll
            for (int mi = 0; mi < 2; mi++) {
                uint32_t ao = (uint32_t)((a_row + mi * 16) * RS + (ks * 16 + a_kb) * 2);
                ldsm4(ahf[mi], sbase + ao);
                ldsm4(alf[mi], sbase + O_AL + ao);
            }
#pragma unroll
            for (int ng = 0; ng < 4; ng++) {
                uint32_t bh[4];
                uint32_t bo = (uint32_t)((b_row + ng * 16) * RS + (ks * 16 + b_kb) * 2);
                ldsm4(bh, sbase + O_BH + bo);
#pragma unroll
                for (int mi = 0; mi < 2; mi++) {
                    mma_f16(acc[mi][ng * 2],     ahf[mi], bh);
                    mma_f16(acc[mi][ng * 2 + 1], ahf[mi], bh + 2);
                    mma_f16(acc[mi][ng * 2],     alf[mi], bh);
                    mma_f16(acc[mi][ng * 2 + 1], alf[mi], bh + 2);
                }
            }
        }
        __syncthreads();
    }

    int r_lane = lane >> 2, c_lane = (lane & 3) << 1;
#pragma unroll
    for (int mi = 0; mi < 2; mi++) {
#pragma unroll
        for (int ni = 0; ni < 8; ni++) {
            long r = row0 + mw * 32 + mi * 16 + r_lane;
            long c = col0 + wc * 64 + ni * 8 + c_lane;
            float b0 = bias[c], b1 = bias[c + 1];
            float2 v0 = {acc[mi][ni][0] + b0, acc[mi][ni][1] + b1};
            float2 v1 = {acc[mi][ni][2] + b0, acc[mi][ni][3] + b1};
            if (EPI == 1) {
                float2 r0 = *(const float2*)(res + r * Nc + c);
                float2 r1 = *(const float2*)(res + (r + 8) * Nc + c);
                v0.x += r0.x; v0.y += r0.y;
                v1.x += r1.x; v1.y += r1.y;
            }
            *(float2*)(out + r * Nc + c) = v0;
            *(float2*)(out + (r + 8) * Nc + c) = v1;
        }
    }
}

// ---------------- batched weight transpose+fp16: exact grid, 1024 blocks ------
__global__ void wsplit_all(const float* __restrict__ q_w,  const float* __restrict__ sr_w,
                           const float* __restrict__ kv_w, const float* __restrict__ proj_w,
                           const float* __restrict__ fc1_w,const float* __restrict__ fc2_w) {
    int bid = blockIdx.x;
    const float* W; int K, N, nbx; size_t off; int lid;
    if (bid < 64)        { W = q_w;    K = 256;  N = 256;  off = OFF_Q;  lid = bid;        nbx = 8;  }
    else if (bid < 320)  { W = sr_w;   K = 1024; N = 256;  off = OFF_SR; lid = bid - 64;   nbx = 8;  }
    else if (bid < 448)  { W = kv_w;   K = 256;  N = 512;  off = OFF_KV; lid = bid - 320;  nbx = 16; }
    else if (bid < 512)  { W = proj_w; K = 256;  N = 256;  off = OFF_PJ; lid = bid - 448;  nbx = 8;  }
    else if (bid < 768)  { W = fc1_w;  K = 256;  N = 1024; off = OFF_F1; lid = bid - 512;  nbx = 32; }
    else                 { W = fc2_w;  K = 1024; N = 256;  off = OFF_F2; lid = bid - 768;  nbx = 8;  }
    int nb = (lid % nbx) * 32, kb = (lid / nbx) * 32;
    __shared__ float t[32][33];
    int tx = threadIdx.x, ty = threadIdx.y;
    t[ty][tx] = W[(size_t)(kb + ty) * N + nb + tx];
    __syncthreads();
    g_wh[off + (size_t)(nb + ty) * K + kb + tx] = __float2half(t[tx][ty]);
}

// ---------------- LayerNorm, warp-per-row (8 rows / 256-thread block) ----------------
template<int WF32, int WSPL>
__global__ void ln256_kernel(const float* __restrict__ in, float* __restrict__ out,
                             const float* __restrict__ w, const float* __restrict__ b) {
    int warp = threadIdx.x >> 5, lane = threadIdx.x & 31;
    long row = (long)blockIdx.x * 8 + warp;
    const float4* ip = (const float4*)(in + row * CC);
    float4 v0 = ip[lane * 2], v1 = ip[lane * 2 + 1];
    float s = v0.x + v0.y + v0.z + v0.w + v1.x + v1.y + v1.z + v1.w;
    s = warp_sum(s);
    float mean = __shfl_sync(0xffffffffu, s, 0) * (1.0f / CC);
    float c0[8] = {v0.x - mean, v0.y - mean, v0.z - mean, v0.w - mean,
                   v1.x - mean, v1.y - mean, v1.z - mean, v1.w - mean};
    float s2 = 0.f;
#pragma unroll
    for (int e = 0; e < 8; e++) s2 += c0[e] * c0[e];
    s2 = warp_sum(s2);
    float rstd = rsqrtf(__shfl_sync(0xffffffffu, s2, 0) * (1.0f / CC) + LN_EPS);
    const float4* wp = (const float4*)(w) + lane * 2;
    const float4* bp = (const float4*)(b) + lane * 2;
    float4 w0 = wp[0], w1 = wp[1], b0 = bp[0], b1 = bp[1];
    float o[8];
    o[0] = c0[0] * rstd * w0.x + b0.x;  o[1] = c0[1] * rstd * w0.y + b0.y;
    o[2] = c0[2] * rstd * w0.z + b0.z;  o[3] = c0[3] * rstd * w0.w + b0.w;
    o[4] = c0[4] * rstd * w1.x + b1.x;  o[5] = c0[5] * rstd * w1.y + b1.y;
    o[6] = c0[6] * rstd * w1.z + b1.z;  o[7] = c0[7] * rstd * w1.w + b1.w;
    size_t g = (size_t)row * CC + lane * 8;
    if (WF32) {
        float4 q0 = {o[0], o[1], o[2], o[3]}, q1 = {o[4], o[5], o[6], o[7]};
        *(float4*)(out + g) = q0;
        *(float4*)(out + g + 4) = q1;
    }
    if (WSPL) {
        __align__(16) __half hb[8], lb[8];
#pragma unroll
        for (int e = 0; e < 8; e++) split_h(o[e], hb[e], lb[e]);
        *(uint4*)(g_ah + g) = *(uint4*)hb;
        *(uint4*)(g_al + g) = *(uint4*)lb;
    }
}

// ---------------- token2map tmp + fused conf: one 2x2 pixel block per CTA ----------
__global__ void t2m_tmp_kernel(const float* __restrict__ xn, const float* __restrict__ tscore,
                               const int* __restrict__ idx) {
    int g = blockIdx.x;                   // b*MKV + m  (2x2 block id)
    int b = g / MKV, m = g - b * MKV;
    int r2 = m / 28, c2 = m - r2 * 28;
    int p = threadIdx.x >> 6;             // 0..3 : (dy,dx)
    int dy = p >> 1, dx = p & 1;
    int t = threadIdx.x & 63;
    int hw = (2 * r2 + dy) * HH + 2 * c2 + dx;
    int gi = (2 * (2 * r2 + dy)) * HINIT + 2 * (2 * c2 + dx);
    const int* ib = idx + (size_t)b * (HINIT * HINIT);
    int t0 = ib[gi], t1 = ib[gi + 1], t2 = ib[gi + HINIT], t3 = ib[gi + HINIT + 1];
    const float4* x0 = (const float4*)(xn + ((size_t)b * NTOK + t0) * CC);
    const float4* x1 = (const float4*)(xn + ((size_t)b * NTOK + t1) * CC);
    const float4* x2 = (const float4*)(xn + ((size_t)b * NTOK + t2) * CC);
    const float4* x3 = (const float4*)(xn + ((size_t)b * NTOK + t3) * CC);
    float4 a = x0[t], b4 = x1[t], c4 = x2[t], d4 = x3[t];
    float4 o;
    o.x = W4 * (a.x + b4.x + c4.x + d4.x);
    o.y = W4 * (a.y + b4.y + c4.y + d4.y);
    o.z = W4 * (a.z + b4.z + c4.z + d4.z);
    o.w = W4 * (a.w + b4.w + c4.w + d4.w);
    ((float4*)(g_kvmap + ((size_t)b * HWSZ + hw) * CC))[t] = o;
    __shared__ float cf[4];
    if (t == 0) {
        const float* ts = tscore + (size_t)b * NTOK;
        cf[p] = W4 * (ts[t0] + ts[t1] + ts[t2] + ts[t3]);
    }
    __syncthreads();
    if (threadIdx.x == 0)
        g_conf[g] = 0.25f * (cf[0] + cf[1] + cf[2] + cf[3]);
}

// ---------------- fused attention: branchy online softmax, f32x2, 256 thr ----------
__global__ void attn_kernel(const float* __restrict__ q, const float* __restrict__ kv2,
                            const float* __restrict__ conf) {
    const int KT = 112;
    const int DP = DH / 2;
    int bh = blockIdx.x;
    int b = bh / HEADS, h = bh - b * HEADS;
    int n = blockIdx.y * 256 + threadIdx.x;
    bool valid = n < NTOK;
    __shared__ float ksh[KT][DH];
    __shared__ float vsh[KT][DH];
    __shared__ float csh[KT];
    const float scale = 0.17677669529663687f;
    u64 q2[DP], oa2[DP];
#pragma unroll
    for (int k = 0; k < DP; k++) { q2[k] = 0ull; oa2[k] = 0ull; }
    if (valid) {
        const float* qp = q + ((size_t)b * NTOK + n) * CC + h * DH;
#pragma unroll
        for (int k = 0; k < DP; k++) q2[k] = pack2(qp[2 * k] * scale, qp[2 * k + 1] * scale);
    }
    float mrun = -1e30f, lrun = 0.f;
    for (int t = 0; t < 7; t++) {
        int m0 = t * KT;
        __syncthreads();
        for (int i = threadIdx.x; i < KT * DH; i += 256) {
            int mm = i / DH, dd = i - mm * DH;
            size_t base = ((size_t)b * MKV + m0 + mm) * (2 * CC) + h * DH + dd;
            ksh[mm][dd] = kv2[base];
            vsh[mm][dd] = kv2[base + CC];
        }
        if (threadIdx.x < KT) csh[threadIdx.x] = conf[(size_t)b * MKV + m0 + threadIdx.x];
        __syncthreads();
        for (int j = 0; j < KT; j++) {
            const u64* kp = (const u64*)&ksh[j][0];
            u64 s2 = 0ull;
#pragma unroll
            for (int k = 0; k < DP; k++) s2 = fma2(q2[k], kp[k], s2);
            float slo, shi;
            unpack2(s2, slo, shi);
            float s = slo + shi + csh[j];
            const u64* vp = (const u64*)&vsh[j][0];
            if (s <= mrun) {
                float p = __expf(s - mrun);
                lrun += p;
                u64 p2 = pack2s(p);
#pragma unroll
                for (int k = 0; k < DP; k++) oa2[k] = fma2(p2, vp[k], oa2[k]);
            } else {
                float corr = __expf(mrun - s);
                lrun = lrun * corr + 1.0f;
                u64 corr2 = pack2s(corr);
#pragma unroll
                for (int k = 0; k < DP; k++) oa2[k] = fma2(oa2[k], corr2, vp[k]);
                mrun = s;
            }
        }
    }
    if (valid) {
        float inv = 1.0f / lrun;
        size_t op = ((size_t)b * NTOK + n) * CC + h * DH;
#pragma unroll
        for (int k = 0; k < DP; k++) {
            float lo, hi;
            unpack2(oa2[k], lo, hi);
            __half h0, l0, h1, l1;
            split_h(lo * inv, h0, l0);
            split_h(hi * inv, h1, l1);
            g_ah[op + 2 * k] = h0;  g_al[op + 2 * k] = l0;
            g_ah[op + 2 * k + 1] = h1;  g_al[op + 2 * k + 1] = l1;
        }
    }
}

// ---------------- fused token2map(h) + tiled depthwise 3x3 ----------------
// grid (49, 8, 8) = (tile, ch-slice, batch), block 256, dyn smem 100*32*16 = 51200 B
__global__ void dwconv_tiled(const float* __restrict__ hin, const int* __restrict__ idx,
                             const float* __restrict__ dww, const float* __restrict__ dwb) {
    extern __shared__ float4 sh[];   // [100][32]
    int tile = blockIdx.x, slice = blockIdx.y, b = blockIdx.z;
    int ty0 = (tile / 7) * 8, tx0 = (tile % 7) * 8;
    const int* ib = idx + (size_t)b * (HINIT * HINIT);
    const float* hbase = hin + (size_t)b * NTOK * HID;
    int co = slice * 32;
    // build 10x10 halo of hmap on the fly: gather 4 token rows per pixel, average
    for (int i = threadIdx.x; i < 3200; i += 256) {
        int px = i >> 5, cl = i & 31;
        int hy = ty0 + (px / 10) - 1, hx = tx0 + (px % 10) - 1;
        float4 v = {0.f, 0.f, 0.f, 0.f};
        if (hy >= 0 && hy < HH && hx >= 0 && hx < HH) {
            int gi = (2 * hy) * HINIT + 2 * hx;
            int t0 = ib[gi], t1 = ib[gi + 1], t2 = ib[gi + HINIT], t3 = ib[gi + HINIT + 1];
            float4 a = ((const float4*)(hbase + (size_t)t0 * HID))[co + cl];
            float4 b4 = ((const float4*)(hbase + (size_t)t1 * HID))[co + cl];
            float4 c4 = ((const float4*)(hbase + (size_t)t2 * HID))[co + cl];
            float4 d4 = ((const float4*)(hbase + (size_t)t3 * HID))[co + cl];
            v.x = W4 * (a.x + b4.x + c4.x + d4.x);
            v.y = W4 * (a.y + b4.y + c4.y + d4.y);
            v.z = W4 * (a.z + b4.z + c4.z + d4.z);
            v.w = W4 * (a.w + b4.w + c4.w + d4.w);
        }
        sh[px * 32 + cl] = v;
    }
    __syncthreads();
    int cl = threadIdx.x & 31;
    int pr = threadIdx.x >> 5;
    int cg = co + cl;
    float4 wreg[9];
#pragma unroll
    for (int j = 0; j < 9; j++) wreg[j] = ((const float4*)dww)[j * 256 + cg];
    float4 bias = ((const float4*)dwb)[cg];
    float4* ob = (float4*)(g_dw + (size_t)b * HWSZ * HID);
#pragma unroll
    for (int pc = 0; pc < 8; pc++) {
        float4 acc = bias;
#pragma unroll
        for (int ky = 0; ky < 3; ky++)
#pragma unroll
            for (int kx = 0; kx < 3; kx++) {
                float4 in = sh[((pr + ky) * 10 + pc + kx) * 32 + cl];
                float4 w = wreg[ky * 3 + kx];
                acc.x = fmaf(in.x, w.x, acc.x);
                acc.y = fmaf(in.y, w.y, acc.y);
                acc.z = fmaf(in.z, w.z, acc.z);
                acc.w = fmaf(in.w, w.w, acc.w);
            }
        ob[(size_t)((ty0 + pr) * HH + tx0 + pc) * 256 + cg] = acc;
    }
}

// ---------------- map2token: token source lists ----------------
__global__ void fillint0_kernel(int* p, int n) {
    int g = blockIdx.x * blockDim.x + threadIdx.x;
    if (g < n) p[g] = 0;
}

__global__ void build_src_kernel(const int* __restrict__ idx) {
    int g = blockIdx.x * blockDim.x + threadIdx.x;
    if (g >= BB * HINIT * HINIT) return;
    int b = g / (HINIT * HINIT), i = g - b * (HINIT * HINIT);
    int tok = idx[(size_t)b * HINIT * HINIT + i];
    int ir = i / HINIT, ic = i - ir * HINIT;
    int hw = (ir >> 1) * HH + (ic >> 1);
    int row = b * NTOK + tok;
    int slot = atomicAdd(&g_tcnt[row], 1);
    if (slot < CAP) g_tsrc[row * CAP + slot] = hw;
}

__global__ void hc_gather_kernel(const float* __restrict__ skipw) {
    int row = blockIdx.x;
    int b = row / NTOK;
    int c4 = threadIdx.x;
    int cnt = g_tcnt[row];
    const float4* dwb = (const float4*)(g_dw + (size_t)b * HWSZ * HID);
    float4 acc = {0.f, 0.f, 0.f, 0.f};
    for (int s = 0; s < cnt; s++) {
        int hw = g_tsrc[row * CAP + s];
        float4 v = dwb[(size_t)hw * 256 + c4];
        acc.x += v.x; acc.y += v.y; acc.z += v.z; acc.w += v.w;
    }
    float inv = 1.0f / ((float)cnt + EPS_C);
    float4 hv = ((const float4*)g_h)[(size_t)row * 256 + c4];
    float4 sw = ((const float4*)skipw)[c4];
    float v[4];
    v[0] = hv.x * sw.x + acc.x * inv;
    v[1] = hv.y * sw.y + acc.y * inv;
    v[2] = hv.z * sw.z + acc.z * inv;
    v[3] = hv.w * sw.w + acc.w * inv;
    __align__(8) __half hb[4], lb[4];
#pragma unroll
    for (int e = 0; e < 4; e++) {
        float gv = 0.5f * v[e] * (1.0f + erff(v[e] * 0.70710678118654752f));
        split_h(gv, hb[e], lb[e]);
    }
    size_t o = (size_t)row * HID + c4 * 4;
    *(uint2*)(g_ah + o) = *(uint2*)hb;
    *(uint2*)(g_al + o) = *(uint2*)lb;
}

// ---------------- launch ----------------
extern "C" void kernel_launch(void* const* d_in, const int* in_sizes, int n_in,
                              void* d_out, int out_size) {
    const float* x       = (const float*)d_in[0];
    const float* tscore  = (const float*)d_in[1];
    const int*   idx     = (const int*)  d_in[2];
    const float* n1w     = (const float*)d_in[3];
    const float* n1b     = (const float*)d_in[4];
    const float* q_w     = (const float*)d_in[5];
    const float* q_b     = (const float*)d_in[6];
    const float* kv_w    = (const float*)d_in[7];
    const float* kv_b    = (const float*)d_in[8];
    const float* sr_w    = (const float*)d_in[9];
    const float* sr_b    = (const float*)d_in[10];
    const float* srn_w   = (const float*)d_in[11];
    const float* srn_b   = (const float*)d_in[12];
    const float* proj_w  = (const float*)d_in[13];
    const float* proj_b  = (const float*)d_in[14];
    const float* n2w     = (const float*)d_in[15];
    const float* n2b     = (const float*)d_in[16];
    const float* fc1_w   = (const float*)d_in[17];
    const float* fc1_b   = (const float*)d_in[18];
    const float* skip_w  = (const float*)d_in[19];
    const float* dw_w    = (const float*)d_in[20];
    const float* dw_b    = (const float*)d_in[21];
    const float* fc2_w   = (const float*)d_in[22];
    const float* fc2_b   = (const float*)d_in[23];
    float* out = (float*)d_out;

    float *xn, *q, *kvcv, *kv2, *x2, *h, *conf, *kvmap;
    int *tcnt;
    __half *ah, *al, *wh;
    cudaGetSymbolAddress((void**)&xn,    g_xn);
    cudaGetSymbolAddress((void**)&q,     g_q);
    cudaGetSymbolAddress((void**)&kvcv,  g_kvcv);
    cudaGetSymbolAddress((void**)&kv2,   g_kv2);
    cudaGetSymbolAddress((void**)&x2,    g_x2);
    cudaGetSymbolAddress((void**)&h,     g_h);
    cudaGetSymbolAddress((void**)&conf,  g_conf);
    cudaGetSymbolAddress((void**)&kvmap, g_kvmap);
    cudaGetSymbolAddress((void**)&tcnt,  g_tcnt);
    cudaGetSymbolAddress((void**)&ah,    g_ah);
    cudaGetSymbolAddress((void**)&al,    g_al);
    cudaGetSymbolAddress((void**)&wh,    g_wh);

    const int DSM = 2 * STG;   // 61440 B
    cudaFuncSetAttribute(tc_gemm<0, 0>, cudaFuncAttributeMaxDynamicSharedMemorySize, DSM);
    cudaFuncSetAttribute(tc_gemm<1, 0>, cudaFuncAttributeMaxDynamicSharedMemorySize, DSM);
    cudaFuncSetAttribute(tc_gemm<0, 1>, cudaFuncAttributeMaxDynamicSharedMemorySize, DSM);
    cudaFuncSetAttribute(dwconv_tiled, cudaFuncAttributeMaxDynamicSharedMemorySize, 51200);

    // independent prep: token source lists + weight fp16 transpose (exact grid)
    fillint0_kernel<<<(BN + 255) / 256, 256>>>(tcnt, BN);
    build_src_kernel<<<(BB * HINIT * HINIT + 255) / 256, 256>>>(idx);
    wsplit_all<<<1024, dim3(32, 32)>>>(q_w, sr_w, kv_w, proj_w, fc1_w, fc2_w);

    // 1. xn = LN(x), + fp16 splits
    ln256_kernel<1, 1><<<BN / 8, 256>>>(x, xn, n1w, n1b);
    // 2. q = xn @ q_w + q_b
    tc_gemm<0, 0><<<dim3(CC / 128, BN / 128), 256, DSM>>>(ah, al, wh + OFF_Q, q_b, nullptr, q, BN, CC, CC, nullptr);
    // 3. token2map(tmp) -> kv_map + conf (fused 2x2 pool)
    t2m_tmp_kernel<<<BM, 256>>>(xn, tscore, idx);
    // 4+5. kvconv = im2col(kv_map) @ sr_w + sr_b (gather fused)
    tc_gemm<0, 1><<<dim3(CC / 128, BM / 128), 256, DSM>>>(nullptr, nullptr, wh + OFF_SR, sr_b, nullptr, kvcv, BM, 1024, CC, kvmap);
    // 6. kvln = LN(kvconv) -> splits only
    ln256_kernel<0, 1><<<BM / 8, 256>>>(kvcv, nullptr, srn_w, srn_b);
    // 7. kv2 = kvln @ kv_w + kv_b
    tc_gemm<0, 0><<<dim3(512 / 128, BM / 128), 256, DSM>>>(ah, al, wh + OFF_KV, kv_b, nullptr, kv2, BM, CC, 512, nullptr);
    // 8. attention -> splits of a
    attn_kernel<<<dim3(BB * HEADS, (NTOK + 255) / 256), 256>>>(q, kv2, conf);
    // 9. x2 = x + a @ proj_w + proj_b
    tc_gemm<1, 0><<<dim3(CC / 128, BN / 128), 256, DSM>>>(ah, al, wh + OFF_PJ, proj_b, x, x2, BN, CC, CC, nullptr);
    // 10. ln2 = LN(x2) -> splits only
    ln256_kernel<0, 1><<<BN / 8, 256>>>(x2, nullptr, n2w, n2b);
    // 11. h = ln2 @ fc1_w + fc1_b
    tc_gemm<0, 0><<<dim3(HID / 128, BN / 128), 256, DSM>>>(ah, al, wh + OFF_F1, fc1_b, nullptr, h, BN, CC, HID, nullptr);
    // 12+13. dw = depthwise3x3(token2map(h)), gather fused into halo load
    dwconv_tiled<<<dim3(49, 8, BB), 256, 51200>>>(h, idx, dw_w, dw_b);
    // 14. hc = gelu(h*skip + gather(dw)/(cnt+eps)) -> splits
    hc_gather_kernel<<<BN, 256>>>(skip_w);
    // 15. out = x2 + hc @ fc2_w + fc2_b
    tc_gemm<1, 0><<<dim3(CC / 128, BN / 128), 256, DSM>>>(ah, al, wh + OFF_F2, fc2_b, x2, out, BN, HID, CC, nullptr);
}